// round 8
// baseline (speedup 1.0000x reference)
#include <cuda_runtime.h>
#include <math_constants.h>

#define G 16
#define NB 8192
#define THREADS 256

typedef unsigned long long u64;

// ---- packed f32x2 helpers (sm_103a) ----
__device__ __forceinline__ u64 fma2(u64 a, u64 b, u64 c) {
    u64 d;
    asm("fma.rn.f32x2 %0, %1, %2, %3;" : "=l"(d) : "l"(a), "l"(b), "l"(c));
    return d;
}
__device__ __forceinline__ u64 mul2(u64 a, u64 b) {
    u64 d;
    asm("mul.rn.f32x2 %0, %1, %2;" : "=l"(d) : "l"(a), "l"(b));
    return d;
}
__device__ __forceinline__ u64 splat2(float v) {
    u64 d;
    asm("mov.b64 %0, {%1, %1};" : "=l"(d) : "f"(v));
    return d;
}
__device__ __forceinline__ float2 unpack2(u64 v) {
    float2 r;
    asm("mov.b64 {%0, %1}, %2;" : "=f"(r.x), "=f"(r.y) : "l"(v));
    return r;
}

// Wk transposed: [h][c] = Wk[c][h], 256x512 floats
__device__ float g_WkT[256 * 512];

__global__ void wkT_kernel(const float* __restrict__ Wk) {
    int idx = blockIdx.x * blockDim.x + threadIdx.x;
    if (idx < 512 * 256) {
        int c = idx >> 8;      // 0..511
        int h = idx & 255;     // 0..255
        g_WkT[h * 512 + c] = Wk[idx];
    }
}

// Dynamic smem (floats):
//   bufA : 8192 f (32KB): x [512][16]; then q [256][16] in lo; kq g8-15 in hi;
//          finally wn-lo [512][8] ([c][g] for g<8) in lo
//   eekq : 4096 f (16KB): ee [256][16]; then kq g0-7 [8][512];
//          finally wn-hi [512][8] ([c][g] for g>=8)
#define SMEM_FLOATS (8192 + 4096 + 16)
#define SMEM_BYTES (SMEM_FLOATS * 4)

__device__ __forceinline__ float* kq_row(float* bufA, float* eekq, int g) {
    return (g < 8) ? (eekq + g * 512) : (bufA + 4096 + (g - 8) * 512);
}

// GEMV, 16 batch-accumulators as 8 packed f32x2, double-buffered weight prefetch.
// xs: smem [KD][16].
template<int KD>
__device__ __forceinline__ void gemv16(const float* __restrict__ Wcol,
                                       const float* __restrict__ xs,
                                       u64 acc[8])
{
    float wreg[8];
    #pragma unroll
    for (int j = 0; j < 8; j++) wreg[j] = __ldg(&Wcol[j << 8]);
    #pragma unroll 1
    for (int c0 = 0; c0 < KD; c0 += 8) {
        float wnxt[8];
        if (c0 + 8 < KD) {
            #pragma unroll
            for (int j = 0; j < 8; j++) wnxt[j] = __ldg(&Wcol[(c0 + 8 + j) << 8]);
        }
        #pragma unroll
        for (int j = 0; j < 8; j++) {
            const float* xp = xs + (c0 + j) * 16;
            ulonglong2 xa = *(const ulonglong2*)(xp + 0);
            ulonglong2 xb = *(const ulonglong2*)(xp + 4);
            ulonglong2 xc = *(const ulonglong2*)(xp + 8);
            ulonglong2 xd = *(const ulonglong2*)(xp + 12);
            u64 wp = splat2(wreg[j]);
            acc[0] = fma2(xa.x, wp, acc[0]);
            acc[1] = fma2(xa.y, wp, acc[1]);
            acc[2] = fma2(xb.x, wp, acc[2]);
            acc[3] = fma2(xb.y, wp, acc[3]);
            acc[4] = fma2(xc.x, wp, acc[4]);
            acc[5] = fma2(xc.y, wp, acc[5]);
            acc[6] = fma2(xd.x, wp, acc[6]);
            acc[7] = fma2(xd.y, wp, acc[7]);
        }
        #pragma unroll
        for (int j = 0; j < 8; j++) wreg[j] = wnxt[j];
    }
}

// 32 neighbors: online softmax, packed f32x2, kq register-resident (R6 form).
__device__ __forceinline__ void attn_seg32(
    const float* __restrict__ relb, const float* __restrict__ nodeb,
    const u64 kqp[8],
    int lane, float& m, float& ssum, u64 waccp[8])
{
    const float* pr = relb + 4 * lane;
    const float* pn = nodeb + 4 * lane;
    #pragma unroll 1
    for (int n = 0; n < 32; n++) {
        ulonglong2 A0 = *(const ulonglong2*)(pr + n * 256);
        ulonglong2 A1 = *(const ulonglong2*)(pr + n * 256 + 128);
        ulonglong2 A2 = *(const ulonglong2*)(pn + n * 256);
        ulonglong2 A3 = *(const ulonglong2*)(pn + n * 256 + 128);

        u64 pp = mul2(A0.x, kqp[0]);
        pp = fma2(A0.y, kqp[1], pp);
        pp = fma2(A1.x, kqp[2], pp);
        pp = fma2(A1.y, kqp[3], pp);
        pp = fma2(A2.x, kqp[4], pp);
        pp = fma2(A2.y, kqp[5], pp);
        pp = fma2(A3.x, kqp[6], pp);
        pp = fma2(A3.y, kqp[7], pp);
        float2 pu = unpack2(pp);
        float p = pu.x + pu.y;
        #pragma unroll
        for (int o = 16; o; o >>= 1) p += __shfl_xor_sync(0xffffffffu, p, o);

        float sn = p * 0.0625f;              // / sqrt(256); q.bk shift cancels in softmax
        if (sn > m) {                        // warp-uniform branch
            float sc = __expf(m - sn);
            ssum *= sc;
            u64 scp = splat2(sc);
            #pragma unroll
            for (int j = 0; j < 8; j++) waccp[j] = mul2(waccp[j], scp);
            m = sn;
        }
        float e = __expf(sn - m);
        ssum += e;
        u64 ep = splat2(e);
        waccp[0] = fma2(ep, A0.x, waccp[0]);
        waccp[1] = fma2(ep, A0.y, waccp[1]);
        waccp[2] = fma2(ep, A1.x, waccp[2]);
        waccp[3] = fma2(ep, A1.y, waccp[3]);
        waccp[4] = fma2(ep, A2.x, waccp[4]);
        waccp[5] = fma2(ep, A2.y, waccp[5]);
        waccp[6] = fma2(ep, A3.x, waccp[6]);
        waccp[7] = fma2(ep, A3.y, waccp[7]);
    }
}

__global__ __launch_bounds__(256, 4)
void superedge_kernel(
    const float* __restrict__ mnode0, const float* __restrict__ mnode1,
    const float* __restrict__ dnode0, const float* __restrict__ dnode1,
    const float* __restrict__ mrel0,  const float* __restrict__ drel0,
    const float* __restrict__ W_edge, const float* __restrict__ b_edge,
    const float* __restrict__ Wq,     const float* __restrict__ bq,
    const float* __restrict__ bk,
    const float* __restrict__ Wv,     const float* __restrict__ bv,
    float* __restrict__ out)
{
    extern __shared__ float smem[];
    float* bufA = smem;            // 8192 f
    float* eekq = smem + 8192;     // 4096 f

    const int tid = threadIdx.x;
    const int b0 = blockIdx.x * G;
    const int w = tid >> 5, lane = tid & 31;

    // ---------------- Phase 1: x = [mnode0 | dnode0] -> bufA[c][g], c in [0,512)
    #pragma unroll
    for (int g = 0; g < G; g++) {
        int b = b0 + g;
        bufA[tid * 16 + g]         = mnode0[(size_t)b * 256 + tid];
        bufA[(tid + 256) * 16 + g] = dnode0[(size_t)b * 256 + tid];
    }
    __syncthreads();

    u64 acc[8];

    // ---------------- Phase 2: edge_emb[h=tid] = relu(x @ W_edge + b_edge)
    {
        u64 bias = splat2(b_edge[tid]);
        #pragma unroll
        for (int i = 0; i < 8; i++) acc[i] = bias;
        gemv16<512>(W_edge + tid, bufA, acc);
        #pragma unroll
        for (int i = 0; i < 8; i++) {
            float2 r = unpack2(acc[i]);
            float v0 = fmaxf(r.x, 0.0f);
            float v1 = fmaxf(r.y, 0.0f);
            eekq[tid * 16 + 2 * i]     = v0;   // ee [256][16]
            eekq[tid * 16 + 2 * i + 1] = v1;
            out[(size_t)(b0 + 2 * i) * 512 + tid]     = v0;
            out[(size_t)(b0 + 2 * i + 1) * 512 + tid] = v1;
        }
    }
    __syncthreads();

    // ---------------- Phase 3: q[h=tid] = ee @ Wq + bq -> bufA lo [256][16]
    {
        u64 bias = splat2(bq[tid]);
        #pragma unroll
        for (int i = 0; i < 8; i++) acc[i] = bias;
        gemv16<256>(Wq + tid, eekq, acc);
        __syncthreads();   // everyone done reading x-hi? (x fully dead) and ee before q write overlaps x-lo
        #pragma unroll
        for (int i = 0; i < 8; i++) {
            float2 r = unpack2(acc[i]);
            bufA[tid * 16 + 2 * i]     = r.x;   // q [256][16] in bufA lo
            bufA[tid * 16 + 2 * i + 1] = r.y;
        }
    }
    __syncthreads();

    // ---------------- Phase 4: kq[g][c] = sum_h WkT[h][c] * q[h][g]
    // two passes: pass p handles c = tid + 256p; 8 u64 accumulators each.
    #pragma unroll 1
    for (int p = 0; p < 2; p++) {
        int c = tid + (p << 8);
        #pragma unroll
        for (int i = 0; i < 8; i++) acc[i] = splat2(0.0f);
        const float* Wc = g_WkT + c;
        float wb[4];
        #pragma unroll
        for (int j = 0; j < 4; j++) wb[j] = __ldg(&Wc[j << 9]);
        #pragma unroll 1
        for (int h0 = 0; h0 < 256; h0 += 4) {
            float wn[4];
            if (h0 + 4 < 256) {
                #pragma unroll
                for (int j = 0; j < 4; j++) wn[j] = __ldg(&Wc[(h0 + 4 + j) << 9]);
            }
            #pragma unroll
            for (int j = 0; j < 4; j++) {
                const float* qp = bufA + (h0 + j) * 16;
                ulonglong2 qa = *(const ulonglong2*)(qp + 0);
                ulonglong2 qb = *(const ulonglong2*)(qp + 4);
                ulonglong2 qc = *(const ulonglong2*)(qp + 8);
                ulonglong2 qd = *(const ulonglong2*)(qp + 12);
                u64 wp = splat2(wb[j]);
                acc[0] = fma2(qa.x, wp, acc[0]);
                acc[1] = fma2(qa.y, wp, acc[1]);
                acc[2] = fma2(qb.x, wp, acc[2]);
                acc[3] = fma2(qb.y, wp, acc[3]);
                acc[4] = fma2(qc.x, wp, acc[4]);
                acc[5] = fma2(qc.y, wp, acc[5]);
                acc[6] = fma2(qd.x, wp, acc[6]);
                acc[7] = fma2(qd.y, wp, acc[7]);
            }
            #pragma unroll
            for (int j = 0; j < 4; j++) wb[j] = wn[j];
        }
        if (p == 0) __syncthreads();   // q reads done before kq g0-7 overwrite ee? (ee dead; this
                                       // barrier orders pass-0 q reads vs nothing harmful; keep for
                                       // symmetry of the hi-write below)
        // write: g 0..7 -> eekq[g*512+c] (ee dead); g 8..15 -> bufA hi (x dead)
        #pragma unroll
        for (int i = 0; i < 8; i++) {
            float2 r = unpack2(acc[i]);
            int g0 = 2 * i, g1 = 2 * i + 1;
            kq_row(bufA, eekq, g0)[c] = r.x;
            kq_row(bufA, eekq, g1)[c] = r.y;
        }
    }
    __syncthreads();

    // ---------------- Phase 5: warp w owns batches 2w, 2w+1; kq in regs; wn over own kq row
    #pragma unroll 1
    for (int gi = 0; gi < 2; gi++) {
        const int g = 2 * w + gi;
        const int b = b0 + g;
        float* kqg = kq_row(bufA, eekq, g);

        u64 kqr[8];
        {
            ulonglong2 k0 = *(const ulonglong2*)&kqg[4 * lane];
            ulonglong2 k1 = *(const ulonglong2*)&kqg[128 + 4 * lane];
            ulonglong2 k2 = *(const ulonglong2*)&kqg[256 + 4 * lane];
            ulonglong2 k3 = *(const ulonglong2*)&kqg[384 + 4 * lane];
            kqr[0] = k0.x; kqr[1] = k0.y;
            kqr[2] = k1.x; kqr[3] = k1.y;
            kqr[4] = k2.x; kqr[5] = k2.y;
            kqr[6] = k3.x; kqr[7] = k3.y;
        }

        float m = -CUDART_INF_F, ssum = 0.0f;
        u64 waccp[8];
        #pragma unroll
        for (int j = 0; j < 8; j++) waccp[j] = splat2(0.0f);

        attn_seg32(mrel0 + (size_t)b * 32 * 256, mnode1 + (size_t)b * 32 * 256,
                   kqr, lane, m, ssum, waccp);
        attn_seg32(drel0 + (size_t)b * 32 * 256, dnode1 + (size_t)b * 32 * 256,
                   kqr, lane, m, ssum, waccp);

        u64 invp = splat2(1.0f / ssum);
        // wn[g][c], c = ch*128 + 4*lane + 2k(+1), stored over this warp's own kq row
        #pragma unroll
        for (int ch = 0; ch < 4; ch++) {
            #pragma unroll
            for (int k = 0; k < 2; k++) {
                u64 v = mul2(waccp[ch * 2 + k], invp);
                *(u64*)&kqg[ch * 128 + 4 * lane + 2 * k] = v;
            }
        }
    }
    __syncthreads();

    // ---------------- Transpose wn [g][c] -> [c][g] half-buffers
    // Stage A: g 0..7 (src eekq) -> bufA lo as [512][8] (q dead)
    {
        int c0 = tid * 2;
        #pragma unroll
        for (int cc = 0; cc < 2; cc++) {
            int c = c0 + cc;
            float4 v0, v1;
            v0.x = eekq[0 * 512 + c]; v0.y = eekq[1 * 512 + c];
            v0.z = eekq[2 * 512 + c]; v0.w = eekq[3 * 512 + c];
            v1.x = eekq[4 * 512 + c]; v1.y = eekq[5 * 512 + c];
            v1.z = eekq[6 * 512 + c]; v1.w = eekq[7 * 512 + c];
            *(float4*)&bufA[c * 8 + 0] = v0;
            *(float4*)&bufA[c * 8 + 4] = v1;
        }
    }
    __syncthreads();
    // Stage B: g 8..15 (src bufA hi) -> eekq as [512][8]
    {
        int c0 = tid * 2;
        #pragma unroll
        for (int cc = 0; cc < 2; cc++) {
            int c = c0 + cc;
            float4 v0, v1;
            v0.x = bufA[4096 + 0 * 512 + c]; v0.y = bufA[4096 + 1 * 512 + c];
            v0.z = bufA[4096 + 2 * 512 + c]; v0.w = bufA[4096 + 3 * 512 + c];
            v1.x = bufA[4096 + 4 * 512 + c]; v1.y = bufA[4096 + 5 * 512 + c];
            v1.z = bufA[4096 + 6 * 512 + c]; v1.w = bufA[4096 + 7 * 512 + c];
            *(float4*)&eekq[c * 8 + 0] = v0;
            *(float4*)&eekq[c * 8 + 4] = v1;
        }
    }
    __syncthreads();

    // ---------------- Phase 6: local_edge[h=tid] = wn @ Wv + bv
    // wn: g 0..7 at bufA[c*8+g], g 8..15 at eekq[c*8+(g-8)]
    {
        u64 bias = splat2(bv[tid]);
        #pragma unroll
        for (int i = 0; i < 8; i++) acc[i] = bias;
        const float* Wcol = Wv + tid;
        float wreg[8];
        #pragma unroll
        for (int j = 0; j < 8; j++) wreg[j] = __ldg(&Wcol[j << 8]);
        #pragma unroll 1
        for (int c0 = 0; c0 < 512; c0 += 8) {
            float wnxt[8];
            if (c0 + 8 < 512) {
                #pragma unroll
                for (int j = 0; j < 8; j++) wnxt[j] = __ldg(&Wcol[(c0 + 8 + j) << 8]);
            }
            #pragma unroll
            for (int j = 0; j < 8; j++) {
                int c = c0 + j;
                ulonglong2 xa = *(const ulonglong2*)&bufA[c * 8 + 0];
                ulonglong2 xb = *(const ulonglong2*)&bufA[c * 8 + 4];
                ulonglong2 xc = *(const ulonglong2*)&eekq[c * 8 + 0];
                ulonglong2 xd = *(const ulonglong2*)&eekq[c * 8 + 4];
                u64 wp = splat2(wreg[j]);
                acc[0] = fma2(xa.x, wp, acc[0]);
                acc[1] = fma2(xa.y, wp, acc[1]);
                acc[2] = fma2(xb.x, wp, acc[2]);
                acc[3] = fma2(xb.y, wp, acc[3]);
                acc[4] = fma2(xc.x, wp, acc[4]);
                acc[5] = fma2(xc.y, wp, acc[5]);
                acc[6] = fma2(xd.x, wp, acc[6]);
                acc[7] = fma2(xd.y, wp, acc[7]);
            }
            #pragma unroll
            for (int j = 0; j < 8; j++) wreg[j] = wnxt[j];
        }
        #pragma unroll
        for (int i = 0; i < 8; i++) {
            float2 r = unpack2(acc[i]);
            out[(size_t)(b0 + 2 * i) * 512 + 256 + tid]     = r.x;
            out[(size_t)(b0 + 2 * i + 1) * 512 + 256 + tid] = r.y;
        }
    }
}

extern "C" void kernel_launch(void* const* d_in, const int* in_sizes, int n_in,
                              void* d_out, int out_size) {
    const float* mnode0 = (const float*)d_in[0];
    const float* mnode1 = (const float*)d_in[1];
    const float* dnode0 = (const float*)d_in[2];
    const float* dnode1 = (const float*)d_in[3];
    const float* mrel0  = (const float*)d_in[4];
    const float* drel0  = (const float*)d_in[5];
    const float* W_edge = (const float*)d_in[6];
    const float* b_edge = (const float*)d_in[7];
    const float* Wq     = (const float*)d_in[8];
    const float* bq     = (const float*)d_in[9];
    const float* Wk     = (const float*)d_in[10];
    const float* bk     = (const float*)d_in[11];
    const float* Wv     = (const float*)d_in[12];
    const float* bv     = (const float*)d_in[13];
    float* out = (float*)d_out;

    cudaFuncSetAttribute(superedge_kernel,
                         cudaFuncAttributeMaxDynamicSharedMemorySize, SMEM_BYTES);

    wkT_kernel<<<512, 256>>>(Wk);
    superedge_kernel<<<NB / G, THREADS, SMEM_BYTES>>>(
        mnode0, mnode1, dnode0, dnode1, mrel0, drel0,
        W_edge, b_edge, Wq, bq, bk, Wv, bv, out);
}